// round 11
// baseline (speedup 1.0000x reference)
#include <cuda_runtime.h>
#include <stdint.h>
#include <math.h>

// ---------------- problem dims ----------------
#define NFEAT  6
#define PAIRS  15
#define EMBED  256
#define TOKENS 16384          // B*S
#define KCAT   512            // 2*EMBED

// ---------------- CTA tiling ----------------
// grid = TOKENS/64 = 256 CTAs, 256 threads (8 warps), warp grid 1(m) x 8(n)
// warp tile 64(m) x 32(n): 4 m16 x 4 n8 of m16n8k8 tf32 mma
// BK=32: 16 stage-1 k-tiles + 8 stage-2 k-tiles per pair -> half the barriers of BK=16.
#define BM 64
#define BN 256
#define BK 32

// ---------------- smem layout (u32 units) ----------------
#define ASTR 72               // A/H k-row stride (64 cols + 8 pad)
#define BSTR 264              // B k-row stride (256 cols + 8 pad)
#define AS_BUF (BK * ASTR)    // 2304 u32
#define BS_BUF (BK * BSTR)    // 8448 u32
#define OFF_AS 0
#define OFF_BS (2 * AS_BUF)                 // 4608
#define OFF_HS (OFF_BS + 2 * BS_BUF)        // 4608 + 16896 = 21504
#define SMEM_U32 (OFF_HS + 256 * ASTR)      // 21504 + 18432 = 39936
#define SMEM_BYTES (SMEM_U32 * 4)           // 159744 B (1 CTA/SM)

#define NT_S1 16              // stage-1 k-tiles (K=512, BK=32)
#define NT_S2 8               // stage-2 k-tiles (K=256, BK=32)

__constant__ int c_pi[PAIRS] = {0,0,0,0,0,1,1,1,1,2,2,2,3,3,4};
__constant__ int c_pj[PAIRS] = {1,2,3,4,5,2,3,4,5,3,4,5,4,5,5};

// ---------------- helpers ----------------
__device__ __forceinline__ uint32_t f2tf(float x) {
    uint32_t u; asm("cvt.rn.tf32.f32 %0, %1;" : "=r"(u) : "f"(x)); return u;
}
__device__ __forceinline__ float fast_tanh(float x) {
    float ax = fabsf(x);
    float e; asm("ex2.approx.f32 %0, %1;" : "=f"(e) : "f"(-2.8853900817779268f * ax));
    float d; asm("rcp.approx.f32 %0, %1;" : "=f"(d) : "f"(1.0f + e));
    float t = (1.0f - e) * d;
    return copysignf(t, x);
}
__device__ __forceinline__ void mma_tf32(float* c, const uint32_t* a, const uint32_t* b) {
    asm volatile(
        "mma.sync.aligned.m16n8k8.row.col.f32.tf32.tf32.f32 "
        "{%0,%1,%2,%3}, {%4,%5,%6,%7}, {%8,%9}, {%0,%1,%2,%3};\n"
        : "+f"(c[0]), "+f"(c[1]), "+f"(c[2]), "+f"(c[3])
        : "r"(a[0]), "r"(a[1]), "r"(a[2]), "r"(a[3]), "r"(b[0]), "r"(b[1]));
}
__device__ __forceinline__ int pair_active(int p, const int* __restrict__ NAS) {
    const int fi = c_pi[p], fj = c_pj[p];
    return ((fi < 2) ? 1 : NAS[fi]) * ((fj < 2) ? 1 : NAS[fj]);
}

// One BK=32 tile: 4 blocks of k8 -> 64 MMAs per warp between barriers.
// A rows stride ASTR, cols add-swizzled: col' = (m + ((k&12)<<1)) & 63.
__device__ __forceinline__ void tile_mma(const uint32_t* __restrict__ bufA,
                                         const uint32_t* __restrict__ bufB,
                                         int tig, int g, int wn,
                                         float acc[4][4][4]) {
    #pragma unroll
    for (int ks8 = 0; ks8 < 4; ks8++) {
        const int ks = ks8 * 8;
        const uint32_t* Ak0 = bufA + (ks + tig) * ASTR;
        const uint32_t* Ak4 = bufA + (ks + tig + 4) * ASTR;
        const int o0 = (ks & 12) << 1;
        const int o4 = ((ks + 4) & 12) << 1;
        uint32_t a[4][4];
        #pragma unroll
        for (int mi = 0; mi < 4; mi++) {
            const int m = mi * 16 + g;
            a[mi][0] = Ak0[(m + o0) & 63];
            a[mi][1] = Ak0[(m + 8 + o0) & 63];
            a[mi][2] = Ak4[(m + o4) & 63];
            a[mi][3] = Ak4[(m + 8 + o4) & 63];
        }
        const uint32_t* Bk0 = bufB + (ks + tig) * BSTR + wn + g;
        const uint32_t* Bk4 = bufB + (ks + tig + 4) * BSTR + wn + g;
        uint32_t b[4][2];
        #pragma unroll
        for (int ni = 0; ni < 4; ni++) { b[ni][0] = Bk0[ni * 8]; b[ni][1] = Bk4[ni * 8]; }
        #pragma unroll
        for (int mi = 0; mi < 4; mi++)
            #pragma unroll
            for (int ni = 0; ni < 4; ni++)
                mma_tf32(acc[mi][ni], a[mi], b[ni]);
    }
}

// ---------------- fused kernel ----------------
__global__ __launch_bounds__(256, 1) void fused_kernel(
    const float* __restrict__ features,
    const float* __restrict__ W_pair,
    const float* __restrict__ b_pair,
    const float* __restrict__ W_final,
    const float* __restrict__ b_final,
    const int* __restrict__ NAS,
    float* __restrict__ out)
{
    extern __shared__ uint32_t sm[];
    uint32_t* const smA = sm + OFF_AS;
    uint32_t* const smB = sm + OFF_BS;
    uint32_t* const Hs  = sm + OFF_HS;

    const int tid = threadIdx.x;
    const int lane = tid & 31, wid = tid >> 5;
    const int g = lane >> 2, tig = lane & 3;
    const int wn = wid * 32;
    const int row0 = blockIdx.x * BM;

    // A loader: 64 rows x 32 k per tile; thread -> (row, kb) and (row, kb+16)
    const int a_row = tid >> 2;            // 0..63
    const int a_kb  = (tid & 3) * 4;       // 0,4,8,12
    const int a_col = (a_row + 2 * a_kb) & 63;   // swizzle col (same for both k halves)

    // B loader: 32 rows x 256 per tile; thread -> rows (b_row, b_row+16), 16 floats each
    const int b_row  = tid >> 4;           // 0..15
    const int b_fcol = (tid & 15) * 16;    // float col

#define LOAD_A(Ab, kt) do { \
        const float* s_ = (Ab) + (size_t)a_row * EMBED + (kt) * 32 + a_kb; \
        av0 = *(const float4*)s_; \
        av1 = *(const float4*)(s_ + 16); \
    } while (0)
#define STORE_A(bufp) do { \
        uint32_t* d_ = (bufp) + a_kb * ASTR + a_col; \
        d_[0 * ASTR] = f2tf(av0.x); d_[1 * ASTR] = f2tf(av0.y); \
        d_[2 * ASTR] = f2tf(av0.z); d_[3 * ASTR] = f2tf(av0.w); \
        d_[(16 + 0) * ASTR] = f2tf(av1.x); d_[(16 + 1) * ASTR] = f2tf(av1.y); \
        d_[(16 + 2) * ASTR] = f2tf(av1.z); d_[(16 + 3) * ASTR] = f2tf(av1.w); \
    } while (0)
#define LOAD_B(srcbase) do { \
        const float* s0_ = (srcbase) + (size_t)b_row * EMBED + b_fcol; \
        const float* s1_ = s0_ + 16 * EMBED; \
        _Pragma("unroll") \
        for (int q_ = 0; q_ < 4; q_++) { \
            bv[q_]     = *(const float4*)(s0_ + q_ * 4); \
            bv[4 + q_] = *(const float4*)(s1_ + q_ * 4); \
        } \
    } while (0)
#define STORE_B(bufp) do { \
        uint32_t* d0_ = (bufp) + b_row * BSTR + b_fcol; \
        uint32_t* d1_ = d0_ + 16 * BSTR; \
        _Pragma("unroll") \
        for (int q_ = 0; q_ < 4; q_++) { \
            uint4 w_; \
            w_.x = f2tf(bv[q_].x); w_.y = f2tf(bv[q_].y); \
            w_.z = f2tf(bv[q_].z); w_.w = f2tf(bv[q_].w); \
            *(uint4*)(d0_ + q_ * 4) = w_; \
            w_.x = f2tf(bv[4+q_].x); w_.y = f2tf(bv[4+q_].y); \
            w_.z = f2tf(bv[4+q_].z); w_.w = f2tf(bv[4+q_].w); \
            *(uint4*)(d1_ + q_ * 4) = w_; \
        } \
    } while (0)

    float oacc[4][4][4];
    #pragma unroll
    for (int mi = 0; mi < 4; mi++)
        #pragma unroll
        for (int ni = 0; ni < 4; ni++)
            #pragma unroll
            for (int r = 0; r < 4; r++) oacc[mi][ni][r] = 0.f;

    #pragma unroll 1
    for (int p = 0; p < PAIRS; p++) {
        if (!pair_active(p, NAS)) continue;
        const int fi = c_pi[p], fj = c_pj[p];
        const float* Ai = features + ((size_t)fi * TOKENS + row0) * EMBED;
        const float* Aj = features + ((size_t)fj * TOKENS + row0) * EMBED;
        const float* Wp = W_pair + (size_t)p * KCAT * EMBED;
        const float* Wf = W_final + (size_t)p * EMBED * EMBED;

        float hacc[4][4][4];
        #pragma unroll
        for (int mi = 0; mi < 4; mi++)
            #pragma unroll
            for (int ni = 0; ni < 4; ni++)
                #pragma unroll
                for (int r = 0; r < 4; r++) hacc[mi][ni][r] = 0.f;

        float4 av0, av1, bv[8];

        // ---- prologue: tile 0 -> buf0; preload tile-1 regs ----
        LOAD_A(Ai, 0);
        LOAD_B(Wp);
        STORE_A(smA);
        STORE_B(smB);
        LOAD_A(Ai, 1);
        LOAD_B(Wp + 32 * EMBED);
        __syncthreads();

        // ---- stage 1: 16 k-tiles ----
        #pragma unroll 1
        for (int t = 0; t < NT_S1; t++) {
            tile_mma(smA + (t & 1) * AS_BUF, smB + (t & 1) * BS_BUF, tig, g, wn, hacc);
            // store tile t+1 from regs (A only while it exists; B includes Wf tile 0 at t=15)
            if (t + 1 < NT_S1) STORE_A(smA + ((t + 1) & 1) * AS_BUF);
            STORE_B(smB + ((t + 1) & 1) * BS_BUF);
            // prefetch tile t+2 regs
            const int u = t + 2;
            if (u < NT_S1) {
                const float* Ab = (u < 8) ? Ai : Aj;
                const int kt = (u < 8) ? u : (u - 8);
                LOAD_A(Ab, kt);
                LOAD_B(Wp + (size_t)u * 32 * EMBED);
            } else if (u < NT_S1 + NT_S2) {
                LOAD_B(Wf + (size_t)(u - NT_S1) * 32 * EMBED);
            }
            __syncthreads();
        }

        // ---- epilogue 1: tanh -> tf32 RN -> Hs (stage-2 A layout, swizzled) ----
        #pragma unroll
        for (int ni = 0; ni < 4; ni++) {
            const int c = wn + ni * 8 + tig * 2;
            const float2 bb = *(const float2*)&b_pair[p * EMBED + c];
            const int sw = (c & 12) << 1;   // same for c and c+1
            #pragma unroll
            for (int mi = 0; mi < 4; mi++) {
                const int r0 = mi * 16 + g, r1 = r0 + 8;
                Hs[(c    ) * ASTR + ((r0 + sw) & 63)] = f2tf(fast_tanh(hacc[mi][ni][0] + bb.x));
                Hs[(c + 1) * ASTR + ((r0 + sw) & 63)] = f2tf(fast_tanh(hacc[mi][ni][1] + bb.y));
                Hs[(c    ) * ASTR + ((r1 + sw) & 63)] = f2tf(fast_tanh(hacc[mi][ni][2] + bb.x));
                Hs[(c + 1) * ASTR + ((r1 + sw) & 63)] = f2tf(fast_tanh(hacc[mi][ni][3] + bb.y));
            }
        }
        __syncthreads();

        // ---- stage 2: 8 k-tiles from Hs; B pipeline continues ----
        #pragma unroll 1
        for (int s = 0; s < NT_S2; s++) {
            const int t = NT_S1 + s;
            tile_mma(Hs + s * BK * ASTR, smB + (t & 1) * BS_BUF, tig, g, wn, oacc);
            if (s + 1 < NT_S2) STORE_B(smB + ((t + 1) & 1) * BS_BUF);
            if (s + 2 < NT_S2) LOAD_B(Wf + (size_t)(s + 2) * 32 * EMBED);
            __syncthreads();
        }
    }

    // ---- final epilogue: + b_final -> out ----
    #pragma unroll
    for (int ni = 0; ni < 4; ni++) {
        const int c = wn + ni * 8 + tig * 2;
        const float2 bb = *(const float2*)&b_final[c];
        #pragma unroll
        for (int mi = 0; mi < 4; mi++) {
            const int r0 = row0 + mi * 16 + g, r1 = r0 + 8;
            float2 v0 = make_float2(oacc[mi][ni][0] + bb.x, oacc[mi][ni][1] + bb.y);
            float2 v1 = make_float2(oacc[mi][ni][2] + bb.x, oacc[mi][ni][3] + bb.y);
            *(float2*)&out[(size_t)r0 * EMBED + c] = v0;
            *(float2*)&out[(size_t)r1 * EMBED + c] = v1;
        }
    }
#undef LOAD_A
#undef STORE_A
#undef LOAD_B
#undef STORE_B
}

// ---------------- launch ----------------
extern "C" void kernel_launch(void* const* d_in, const int* in_sizes, int n_in,
                              void* d_out, int out_size) {
    const float* features = (const float*)d_in[0];
    const float* W_pair   = (const float*)d_in[1];
    const float* b_pair   = (const float*)d_in[2];
    const float* W_final  = (const float*)d_in[3];
    const float* b_final  = (const float*)d_in[4];
    const int*   NAS      = (const int*)d_in[5];
    float* out = (float*)d_out;

    static int attr_set = 0;
    if (!attr_set) {
        cudaFuncSetAttribute(fused_kernel, cudaFuncAttributeMaxDynamicSharedMemorySize,
                             SMEM_BYTES);
        attr_set = 1;
    }

    fused_kernel<<<TOKENS / BM, 256, SMEM_BYTES>>>(
        features, W_pair, b_pair, W_final, b_final, NAS, out);
}

// round 12
// speedup vs baseline: 1.3121x; 1.3121x over previous
#include <cuda_runtime.h>
#include <stdint.h>
#include <math.h>

// ---------------- problem dims ----------------
#define NFEAT  6
#define PAIRS  15
#define EMBED  256
#define TOKENS 16384          // B*S
#define KCAT   512            // 2*EMBED

// ---------------- CTA tiling ----------------
// grid = TOKENS/128 = 128 CTAs (1 wave on 148 SMs), 256 threads (8 warps)
// warp grid 2(m) x 4(n) -> warp tile 64x64: 4 m16 x 8 n8 of m16n8k8 tf32 mma
// 32 LDS.32 per 32 MMAs per k8 (ratio 1.0 vs 1.5 in the 64x32 variant).
// Single accumulator (128 fl) shared by stage1/stage2; out RMW per active pair.
#define BM 128
#define BN 256
#define BK 16

// ---------------- smem layout (u32 units) ----------------
#define ASTR 136              // A/H k-row stride (128 cols + 8 pad)
#define BSTR 264              // B k-row stride (256 cols + 8 pad)
#define AS_BUF (BK * ASTR)    // 2176 u32
#define BS_BUF (BK * BSTR)    // 4224 u32
#define OFF_AS 0
#define OFF_BS (2 * AS_BUF)                 // 4352
#define OFF_HS (OFF_BS + 2 * BS_BUF)        // 4352 + 8448 = 12800
#define SMEM_U32 (OFF_HS + 256 * ASTR)      // 12800 + 34816 = 47616
#define SMEM_BYTES (SMEM_U32 * 4)           // 190464 B (1 CTA/SM)

#define NT_S1 32              // stage-1 k-tiles (K=512)
#define NT_ALL 48             // + 16 stage-2 k-tiles (K=256)

__constant__ int c_pi[PAIRS] = {0,0,0,0,0,1,1,1,1,2,2,2,3,3,4};
__constant__ int c_pj[PAIRS] = {1,2,3,4,5,2,3,4,5,3,4,5,4,5,5};

// ---------------- helpers ----------------
__device__ __forceinline__ uint32_t f2tf(float x) {
    uint32_t u; asm("cvt.rn.tf32.f32 %0, %1;" : "=r"(u) : "f"(x)); return u;
}
__device__ __forceinline__ float fast_tanh(float x) {
    float ax = fabsf(x);
    float e; asm("ex2.approx.f32 %0, %1;" : "=f"(e) : "f"(-2.8853900817779268f * ax));
    float d; asm("rcp.approx.f32 %0, %1;" : "=f"(d) : "f"(1.0f + e));
    float t = (1.0f - e) * d;
    return copysignf(t, x);
}
__device__ __forceinline__ void mma_tf32(float* c, const uint32_t* a, const uint32_t* b) {
    asm volatile(
        "mma.sync.aligned.m16n8k8.row.col.f32.tf32.tf32.f32 "
        "{%0,%1,%2,%3}, {%4,%5,%6,%7}, {%8,%9}, {%0,%1,%2,%3};\n"
        : "+f"(c[0]), "+f"(c[1]), "+f"(c[2]), "+f"(c[3])
        : "r"(a[0]), "r"(a[1]), "r"(a[2]), "r"(a[3]), "r"(b[0]), "r"(b[1]));
}
__device__ __forceinline__ int pair_active(int p, const int* __restrict__ NAS) {
    const int fi = c_pi[p], fj = c_pj[p];
    return ((fi < 2) ? 1 : NAS[fi]) * ((fj < 2) ? 1 : NAS[fj]);
}

// One BK=16 tile: 2 k8 blocks. Warp tile 64x64 (4 mi x 8 ni) -> 64 MMAs.
// A rows stride ASTR, cols swizzled: col' = (m + 2*(k&12)) & 127.
__device__ __forceinline__ void tile_mma(const uint32_t* __restrict__ bufA,
                                         const uint32_t* __restrict__ bufB,
                                         int tig, int g, int wm, int wn,
                                         float acc[4][8][4]) {
    #pragma unroll
    for (int ks8 = 0; ks8 < 2; ks8++) {
        const int ks = ks8 * 8;
        const uint32_t* Ak0 = bufA + (ks + tig) * ASTR;
        const uint32_t* Ak4 = bufA + (ks + tig + 4) * ASTR;
        const int o0 = (ks & 12) << 1;
        const int o4 = ((ks + 4) & 12) << 1;
        uint32_t a[4][4];
        #pragma unroll
        for (int mi = 0; mi < 4; mi++) {
            const int m = wm + mi * 16 + g;
            a[mi][0] = Ak0[(m + o0) & 127];
            a[mi][1] = Ak0[(m + 8 + o0) & 127];
            a[mi][2] = Ak4[(m + o4) & 127];
            a[mi][3] = Ak4[(m + 8 + o4) & 127];
        }
        const uint32_t* Bk0 = bufB + (ks + tig) * BSTR + wn + g;
        const uint32_t* Bk4 = bufB + (ks + tig + 4) * BSTR + wn + g;
        uint32_t b[8][2];
        #pragma unroll
        for (int ni = 0; ni < 8; ni++) { b[ni][0] = Bk0[ni * 8]; b[ni][1] = Bk4[ni * 8]; }
        #pragma unroll
        for (int mi = 0; mi < 4; mi++)
            #pragma unroll
            for (int ni = 0; ni < 8; ni++)
                mma_tf32(acc[mi][ni], a[mi], b[ni]);
    }
}

// ---------------- fused kernel ----------------
__global__ __launch_bounds__(256, 1) void fused_kernel(
    const float* __restrict__ features,
    const float* __restrict__ W_pair,
    const float* __restrict__ b_pair,
    const float* __restrict__ W_final,
    const float* __restrict__ b_final,
    const int* __restrict__ NAS,
    float* __restrict__ out)
{
    extern __shared__ uint32_t sm[];
    uint32_t* const smA = sm + OFF_AS;
    uint32_t* const smB = sm + OFF_BS;
    uint32_t* const Hs  = sm + OFF_HS;

    const int tid = threadIdx.x;
    const int lane = tid & 31, wid = tid >> 5;
    const int g = lane >> 2, tig = lane & 3;
    const int wm = (wid >> 2) * 64;     // 2 m-blocks
    const int wn = (wid & 3) * 64;      // 4 n-blocks
    const int row0 = blockIdx.x * BM;

    // A loader: 128 rows x 16 k; thread -> row=tid>>1, 8 consecutive k at kc
    const int a_row = tid >> 1;            // 0..127
    const int a_kc  = (tid & 1) * 8;       // 0 or 8
    const int a_c0  = (a_row + 2 * a_kc) & 127;        // swizzle col for k in [kc,kc+4)
    const int a_c1  = (a_c0 + 8) & 127;                // for k in [kc+4,kc+8)

    // B loader: 16 rows x 256; thread -> row=tid>>4, 16 floats at fcol
    const int b_row  = tid >> 4;           // 0..15
    const int b_fcol = (tid & 15) * 16;

#define LOAD_A(Ab, kt) do { \
        const float* s_ = (Ab) + (size_t)a_row * EMBED + (kt) * 16 + a_kc; \
        av0 = *(const float4*)s_; \
        av1 = *(const float4*)(s_ + 4); \
    } while (0)
#define STORE_A(bufp) do { \
        uint32_t* d_ = (bufp) + a_kc * ASTR; \
        d_[0 * ASTR + a_c0] = f2tf(av0.x); d_[1 * ASTR + a_c0] = f2tf(av0.y); \
        d_[2 * ASTR + a_c0] = f2tf(av0.z); d_[3 * ASTR + a_c0] = f2tf(av0.w); \
        d_[4 * ASTR + a_c1] = f2tf(av1.x); d_[5 * ASTR + a_c1] = f2tf(av1.y); \
        d_[6 * ASTR + a_c1] = f2tf(av1.z); d_[7 * ASTR + a_c1] = f2tf(av1.w); \
    } while (0)
#define LOAD_B(srcbase) do { \
        const float* s_ = (srcbase) + (size_t)b_row * EMBED + b_fcol; \
        _Pragma("unroll") \
        for (int q_ = 0; q_ < 4; q_++) bv[q_] = *(const float4*)(s_ + q_ * 4); \
    } while (0)
#define STORE_B(bufp) do { \
        uint32_t* d_ = (bufp) + b_row * BSTR + b_fcol; \
        _Pragma("unroll") \
        for (int q_ = 0; q_ < 4; q_++) { \
            uint4 w_; \
            w_.x = f2tf(bv[q_].x); w_.y = f2tf(bv[q_].y); \
            w_.z = f2tf(bv[q_].z); w_.w = f2tf(bv[q_].w); \
            *(uint4*)(d_ + q_ * 4) = w_; \
        } \
    } while (0)

    float acc[4][8][4];
    bool first = true;

    #pragma unroll 1
    for (int p = 0; p < PAIRS; p++) {
        if (!pair_active(p, NAS)) continue;
        const int fi = c_pi[p], fj = c_pj[p];
        const float* Ai = features + ((size_t)fi * TOKENS + row0) * EMBED;
        const float* Aj = features + ((size_t)fj * TOKENS + row0) * EMBED;
        const float* Wp = W_pair + (size_t)p * KCAT * EMBED;
        const float* Wf = W_final + (size_t)p * EMBED * EMBED;

        #pragma unroll
        for (int mi = 0; mi < 4; mi++)
            #pragma unroll
            for (int ni = 0; ni < 8; ni++)
                #pragma unroll
                for (int r = 0; r < 4; r++) acc[mi][ni][r] = 0.f;

        float4 av0, av1, bv[4];

        // ---- prologue: tile 0 -> buf0; preload tile-1 regs ----
        LOAD_A(Ai, 0);
        LOAD_B(Wp);
        STORE_A(smA);
        STORE_B(smB);
        LOAD_A(Ai, 1);
        LOAD_B(Wp + 16 * EMBED);
        __syncthreads();

        // ---- 48 k-tiles: stage1 (0..31, A from smA) + stage2 (32..47, A from Hs) ----
        #pragma unroll 1
        for (int t = 0; t < NT_ALL; t++) {
            const uint32_t* bufA = (t < NT_S1) ? (smA + (t & 1) * AS_BUF)
                                               : (Hs + (t - NT_S1) * AS_BUF);
            tile_mma(bufA, smB + (t & 1) * BS_BUF, tig, g, wm, wn, acc);

            if (t + 1 < NT_S1) STORE_A(smA + ((t + 1) & 1) * AS_BUF);
            if (t + 1 < NT_ALL) STORE_B(smB + ((t + 1) & 1) * BS_BUF);

            const int u = t + 2;
            if (u < NT_S1) {
                const float* Ab = (u < 16) ? Ai : Aj;
                LOAD_A(Ab, u & 15);
                LOAD_B(Wp + (size_t)u * 16 * EMBED);
            } else if (u < NT_ALL) {
                LOAD_B(Wf + (size_t)(u - NT_S1) * 16 * EMBED);
            }
            __syncthreads();

            if (t == NT_S1 - 1) {
                // ---- epilogue 1: tanh -> tf32 RN -> Hs (stage-2 A layout) ----
                #pragma unroll
                for (int ni = 0; ni < 8; ni++) {
                    const int c = wn + ni * 8 + tig * 2;
                    const float2 bb = *(const float2*)&b_pair[p * EMBED + c];
                    const int sw = (c & 12) << 1;   // same for c and c+1
                    #pragma unroll
                    for (int mi = 0; mi < 4; mi++) {
                        const int r0 = wm + mi * 16 + g, r1 = r0 + 8;
                        Hs[(c    ) * ASTR + ((r0 + sw) & 127)] = f2tf(fast_tanh(acc[mi][ni][0] + bb.x));
                        Hs[(c + 1) * ASTR + ((r0 + sw) & 127)] = f2tf(fast_tanh(acc[mi][ni][1] + bb.y));
                        Hs[(c    ) * ASTR + ((r1 + sw) & 127)] = f2tf(fast_tanh(acc[mi][ni][2] + bb.x));
                        Hs[(c + 1) * ASTR + ((r1 + sw) & 127)] = f2tf(fast_tanh(acc[mi][ni][3] + bb.y));
                    }
                }
                #pragma unroll
                for (int mi = 0; mi < 4; mi++)
                    #pragma unroll
                    for (int ni = 0; ni < 8; ni++)
                        #pragma unroll
                        for (int r = 0; r < 4; r++) acc[mi][ni][r] = 0.f;
                __syncthreads();
            }
        }

        // ---- epilogue 2 (per pair): out = / += acc (+ b_final on first) ----
        #pragma unroll
        for (int ni = 0; ni < 8; ni++) {
            const int c = wn + ni * 8 + tig * 2;
            const float2 bb = *(const float2*)&b_final[c];
            #pragma unroll
            for (int mi = 0; mi < 4; mi++) {
                const int r0 = row0 + wm + mi * 16 + g, r1 = r0 + 8;
                float2* o0 = (float2*)&out[(size_t)r0 * EMBED + c];
                float2* o1 = (float2*)&out[(size_t)r1 * EMBED + c];
                float2 v0 = make_float2(acc[mi][ni][0], acc[mi][ni][1]);
                float2 v1 = make_float2(acc[mi][ni][2], acc[mi][ni][3]);
                if (first) {
                    v0.x += bb.x; v0.y += bb.y;
                    v1.x += bb.x; v1.y += bb.y;
                } else {
                    float2 p0 = *o0, p1 = *o1;
                    v0.x += p0.x; v0.y += p0.y;
                    v1.x += p1.x; v1.y += p1.y;
                }
                *o0 = v0;
                *o1 = v1;
            }
        }
        first = false;
    }
#undef LOAD_A
#undef STORE_A
#undef LOAD_B
#undef STORE_B
}

// ---------------- launch ----------------
extern "C" void kernel_launch(void* const* d_in, const int* in_sizes, int n_in,
                              void* d_out, int out_size) {
    const float* features = (const float*)d_in[0];
    const float* W_pair   = (const float*)d_in[1];
    const float* b_pair   = (const float*)d_in[2];
    const float* W_final  = (const float*)d_in[3];
    const float* b_final  = (const float*)d_in[4];
    const int*   NAS      = (const int*)d_in[5];
    float* out = (float*)d_out;

    static int attr_set = 0;
    if (!attr_set) {
        cudaFuncSetAttribute(fused_kernel, cudaFuncAttributeMaxDynamicSharedMemorySize,
                             SMEM_BYTES);
        attr_set = 1;
    }

    fused_kernel<<<TOKENS / BM, 256, SMEM_BYTES>>>(
        features, W_pair, b_pair, W_final, b_final, NAS, out);
}